// round 1
// baseline (speedup 1.0000x reference)
#include <cuda_runtime.h>

// Problem constants
#define B_    2
#define S_    2048
#define HID_  4096
#define NH_   32
#define NKV_  8
#define D_    128
#define GROUPS_ 4

// Scratch (allocation-free: __device__ globals)
__device__ float g_Q[(size_t)B_ * S_ * NH_ * D_];   // [B,S,NH,D]  67MB
__device__ float g_K[(size_t)B_ * S_ * NKV_ * D_];  // [B,S,NKV,D] 17MB
__device__ float g_V[(size_t)B_ * S_ * NKV_ * D_];
__device__ float g_A[(size_t)B_ * S_ * NH_ * D_];   // attn out [B,S,NH*D]

// ---------------- packed f32x2 helpers (sm_100+) ----------------
__device__ __forceinline__ unsigned long long pk2(float x, float y) {
    unsigned long long r;
    asm("mov.b64 %0, {%1, %2};" : "=l"(r) : "f"(x), "f"(y));
    return r;
}
__device__ __forceinline__ void fma2(unsigned long long& d, unsigned long long a, unsigned long long b) {
    asm("fma.rn.f32x2 %0, %1, %2, %0;" : "+l"(d) : "l"(a), "l"(b));
}
__device__ __forceinline__ float2 unpk2(unsigned long long v) {
    float2 f;
    asm("mov.b64 {%0, %1}, %2;" : "=f"(f.x), "=f"(f.y) : "l"(v));
    return f;
}

// ---------------- SGEMM: C[M,N] = A[M,K] @ W[K,N], row-major, fp32 ----------
// 128x128 tile, BK=8, 256 threads, 8x8 microtile (2x2 blocks of 4x4),
// inner product via packed fma.rn.f32x2 (2x FFMA issue rate).
__global__ __launch_bounds__(256) void sgemm_kernel(
    const float* __restrict__ A, const float* __restrict__ W,
    float* __restrict__ C, int M, int N, int K)
{
    __shared__ float As[8][128];
    __shared__ float Bs[8][128];

    const int tid = threadIdx.x;
    const int tx = tid & 15;       // 0..15 (col group)
    const int ty = tid >> 4;       // 0..15 (row group)
    const int bm = blockIdx.y * 128;
    const int bn = blockIdx.x * 128;

    // global-load mapping
    const int arow = tid >> 1;           // 0..127
    const int acol = (tid & 1) * 4;      // 0 or 4
    const int brow = tid >> 5;           // 0..7
    const int bcol = (tid & 31) * 4;     // 0..124

    const float* Aptr = A + (size_t)(bm + arow) * K + acol;
    const float* Bptr = W + (size_t)brow * N + bn + bcol;

    unsigned long long acc2[8][4];
#pragma unroll
    for (int i = 0; i < 8; i++)
#pragma unroll
        for (int j = 0; j < 4; j++) acc2[i][j] = 0ull;  // (0.0f, 0.0f)

    for (int k0 = 0; k0 < K; k0 += 8) {
        float4 av = *(const float4*)(Aptr + k0);
        float4 bv = *(const float4*)(Bptr + (size_t)k0 * N);
        As[acol + 0][arow] = av.x;
        As[acol + 1][arow] = av.y;
        As[acol + 2][arow] = av.z;
        As[acol + 3][arow] = av.w;
        *(float4*)&Bs[brow][bcol] = bv;
        __syncthreads();

#pragma unroll
        for (int kk = 0; kk < 8; kk++) {
            float4 a0 = *(const float4*)&As[kk][ty * 4];
            float4 a1 = *(const float4*)&As[kk][64 + ty * 4];
            // reinterpret 16B smem loads as packed f32x2 pairs (cols j,j+1)
            ulonglong2 bp0 = *(const ulonglong2*)&Bs[kk][tx * 4];
            ulonglong2 bp1 = *(const ulonglong2*)&Bs[kk][64 + tx * 4];
            unsigned long long bb[4] = {bp0.x, bp0.y, bp1.x, bp1.y};
            float a[8] = {a0.x, a0.y, a0.z, a0.w, a1.x, a1.y, a1.z, a1.w};
#pragma unroll
            for (int i = 0; i < 8; i++) {
                unsigned long long ad = pk2(a[i], a[i]);
#pragma unroll
                for (int jp = 0; jp < 4; jp++) fma2(acc2[i][jp], ad, bb[jp]);
            }
        }
        __syncthreads();
    }

#pragma unroll
    for (int ib = 0; ib < 2; ib++) {
#pragma unroll
        for (int i = 0; i < 4; i++) {
            const int ai = ib * 4 + i;
            const int r = bm + ib * 64 + ty * 4 + i;
            float* Crow = C + (size_t)r * N + bn;
#pragma unroll
            for (int jb = 0; jb < 2; jb++) {
                float2 p0 = unpk2(acc2[ai][jb * 2 + 0]);
                float2 p1 = unpk2(acc2[ai][jb * 2 + 1]);
                *(float4*)&Crow[jb * 64 + tx * 4] = make_float4(p0.x, p0.y, p1.x, p1.y);
            }
        }
    }
}

// ---------------- RoPE (in-place, Llama half-rotation) ----------------------
// X layout [B,S,H,D]; grid = B*S*H blocks of 64 threads; positions = arange(S).
__global__ void rope_kernel(float* __restrict__ X,
                            const float* __restrict__ cosc,
                            const float* __restrict__ sinc, int H)
{
    const int idx = blockIdx.x;          // (b*S + s)*H + h
    const int s = (idx / H) % S_;
    const int d = threadIdx.x;           // 0..63
    float* row = X + (size_t)idx * D_;
    const float c0 = cosc[s * D_ + d];
    const float s0 = sinc[s * D_ + d];
    const float c1 = cosc[s * D_ + 64 + d];
    const float s1 = sinc[s * D_ + 64 + d];
    const float x1 = row[d];
    const float x2 = row[d + 64];
    row[d]      = x1 * c0 - x2 * s0;
    row[d + 64] = x2 * c1 + x1 * s1;
}

// ---------------- Causal flash attention (fp32, online softmax) -------------
// 64x64 tiles, D=128. 256 threads: tx=tid%16 (cols/d), ty=tid/16 (rows).
// Each thread: 4 score rows x 4 score cols; O tile rows x 8 d-cols (tx*8+m).
#define QST 132
#define KST 68
#define VST 132
#define PST 68
#define FL_SMEM_BYTES ((64 * QST + 128 * KST + 64 * VST + 64 * PST) * 4)

__global__ __launch_bounds__(256) void flash_kernel(
    const float* __restrict__ Qg, const float* __restrict__ Kg,
    const float* __restrict__ Vg, float* __restrict__ Og)
{
    extern __shared__ float sm[];
    float* Qs  = sm;                    // [64][QST]
    float* Kst = Qs + 64 * QST;         // [128][KST]  (k-major transposed)
    float* Vs  = Kst + 128 * KST;       // [64][VST]
    float* Ps  = Vs + 64 * VST;         // [64][PST]

    const int tid = threadIdx.x;
    const int tx = tid & 15;
    const int ty = tid >> 4;
    const int qt = blockIdx.x;          // 0..31
    const int h  = blockIdx.y;          // 0..31
    const int b  = blockIdx.z;          // 0..1
    const int kvh = h >> 2;             // GROUPS=4
    const int qbase = qt * 64;
    const float scale = 0.08838834764831845f;  // 1/sqrt(128)

    // Load Q tile (pre-scaled)
#pragma unroll
    for (int rep = 0; rep < 8; rep++) {
        int lin = rep * 256 + tid;
        int r = lin >> 5;
        int c4 = (lin & 31) << 2;
        float4 v = *(const float4*)(Qg + ((size_t)((b * S_ + qbase + r) * NH_ + h)) * D_ + c4);
        v.x *= scale; v.y *= scale; v.z *= scale; v.w *= scale;
        *(float4*)&Qs[r * QST + c4] = v;
    }

    float m_i[4], l_i[4], acc[4][8];
#pragma unroll
    for (int i = 0; i < 4; i++) {
        m_i[i] = -1e30f; l_i[i] = 0.f;
#pragma unroll
        for (int m = 0; m < 8; m++) acc[i][m] = 0.f;
    }

    for (int kt = 0; kt <= qt; kt++) {
        const int kbase = kt * 64;
        // Load K (transposed) and V tiles
#pragma unroll
        for (int rep = 0; rep < 8; rep++) {
            int lin = rep * 256 + tid;
            int c = lin >> 5;              // k-position within tile
            int k4 = (lin & 31) << 2;      // d-offset
            size_t gofs = ((size_t)((b * S_ + kbase + c) * NKV_ + kvh)) * D_ + k4;
            float4 kv = *(const float4*)(Kg + gofs);
            Kst[(k4 + 0) * KST + c] = kv.x;
            Kst[(k4 + 1) * KST + c] = kv.y;
            Kst[(k4 + 2) * KST + c] = kv.z;
            Kst[(k4 + 3) * KST + c] = kv.w;
            float4 vv = *(const float4*)(Vg + gofs);
            *(float4*)&Vs[c * VST + k4] = vv;
        }
        __syncthreads();

        // Scores: sc[i][j] = Qs[row] . Kst[:, col]
        float sc[4][4] = {};
#pragma unroll 8
        for (int k = 0; k < D_; k += 4) {
            float4 q0 = *(const float4*)&Qs[(ty * 4 + 0) * QST + k];
            float4 q1 = *(const float4*)&Qs[(ty * 4 + 1) * QST + k];
            float4 q2 = *(const float4*)&Qs[(ty * 4 + 2) * QST + k];
            float4 q3 = *(const float4*)&Qs[(ty * 4 + 3) * QST + k];
            float4 c0 = *(const float4*)&Kst[(k + 0) * KST + tx * 4];
            float4 c1 = *(const float4*)&Kst[(k + 1) * KST + tx * 4];
            float4 c2 = *(const float4*)&Kst[(k + 2) * KST + tx * 4];
            float4 c3 = *(const float4*)&Kst[(k + 3) * KST + tx * 4];
            float qv[4][4] = {{q0.x, q0.y, q0.z, q0.w}, {q1.x, q1.y, q1.z, q1.w},
                              {q2.x, q2.y, q2.z, q2.w}, {q3.x, q3.y, q3.z, q3.w}};
            float kv[4][4] = {{c0.x, c0.y, c0.z, c0.w}, {c1.x, c1.y, c1.z, c1.w},
                              {c2.x, c2.y, c2.z, c2.w}, {c3.x, c3.y, c3.z, c3.w}};
#pragma unroll
            for (int i = 0; i < 4; i++)
#pragma unroll
                for (int kk = 0; kk < 4; kk++)
#pragma unroll
                    for (int j = 0; j < 4; j++)
                        sc[i][j] += qv[i][kk] * kv[kk][j];
        }

        // Causal mask (diagonal tile only; qbase==kbase there)
        if (kt == qt) {
#pragma unroll
            for (int i = 0; i < 4; i++)
#pragma unroll
                for (int j = 0; j < 4; j++)
                    if (tx * 4 + j > ty * 4 + i) sc[i][j] = -1e30f;
        }

        // Online softmax update
#pragma unroll
        for (int i = 0; i < 4; i++) {
            float mloc = fmaxf(fmaxf(sc[i][0], sc[i][1]), fmaxf(sc[i][2], sc[i][3]));
#pragma unroll
            for (int off = 1; off < 16; off <<= 1)
                mloc = fmaxf(mloc, __shfl_xor_sync(0xffffffffu, mloc, off));
            const float mnew = fmaxf(m_i[i], mloc);
            const float fac = __expf(m_i[i] - mnew);
            m_i[i] = mnew;
            l_i[i] *= fac;
#pragma unroll
            for (int m = 0; m < 8; m++) acc[i][m] *= fac;
            float rsum = 0.f;
#pragma unroll
            for (int j = 0; j < 4; j++) {
                float p = __expf(sc[i][j] - mnew);
                sc[i][j] = p;
                rsum += p;
            }
#pragma unroll
            for (int off = 1; off < 16; off <<= 1)
                rsum += __shfl_xor_sync(0xffffffffu, rsum, off);
            l_i[i] += rsum;
            *(float4*)&Ps[(ty * 4 + i) * PST + tx * 4] =
                make_float4(sc[i][0], sc[i][1], sc[i][2], sc[i][3]);
        }
        __syncthreads();

        // PV accumulate: acc[i][m] += P[row][kk] * V[kk][tx*8+m]
#pragma unroll 4
        for (int kk = 0; kk < 64; kk++) {
            float p0 = Ps[(ty * 4 + 0) * PST + kk];
            float p1 = Ps[(ty * 4 + 1) * PST + kk];
            float p2 = Ps[(ty * 4 + 2) * PST + kk];
            float p3 = Ps[(ty * 4 + 3) * PST + kk];
            float4 v0 = *(const float4*)&Vs[kk * VST + tx * 8];
            float4 v1 = *(const float4*)&Vs[kk * VST + tx * 8 + 4];
            float vv[8] = {v0.x, v0.y, v0.z, v0.w, v1.x, v1.y, v1.z, v1.w};
            float pp[4] = {p0, p1, p2, p3};
#pragma unroll
            for (int i = 0; i < 4; i++)
#pragma unroll
                for (int m = 0; m < 8; m++)
                    acc[i][m] += pp[i] * vv[m];
        }
        __syncthreads();
    }

    // Normalize + store [B,S,NH*D]
#pragma unroll
    for (int i = 0; i < 4; i++) {
        const float inv = 1.0f / l_i[i];
        const int r = qbase + ty * 4 + i;
        float* op = Og + ((size_t)((b * S_ + r) * NH_ + h)) * D_ + tx * 8;
        *(float4*)op = make_float4(acc[i][0] * inv, acc[i][1] * inv, acc[i][2] * inv, acc[i][3] * inv);
        *(float4*)(op + 4) = make_float4(acc[i][4] * inv, acc[i][5] * inv, acc[i][6] * inv, acc[i][7] * inv);
    }
}

// ---------------- launch ----------------------------------------------------
extern "C" void kernel_launch(void* const* d_in, const int* in_sizes, int n_in,
                              void* d_out, int out_size)
{
    const float* X    = (const float*)d_in[0];
    const float* Wq   = (const float*)d_in[1];
    const float* Wk   = (const float*)d_in[2];
    const float* Wv   = (const float*)d_in[3];
    const float* Wo   = (const float*)d_in[4];
    const float* cosc = (const float*)d_in[5];
    const float* sinc = (const float*)d_in[6];
    // d_in[7] = position_ids (arange, implicit), d_in[8] = attention_mask (causal, implicit)
    float* out = (float*)d_out;

    float *Qp, *Kp, *Vp, *Ap;
    cudaGetSymbolAddress((void**)&Qp, g_Q);
    cudaGetSymbolAddress((void**)&Kp, g_K);
    cudaGetSymbolAddress((void**)&Vp, g_V);
    cudaGetSymbolAddress((void**)&Ap, g_A);

    const int M = B_ * S_;  // 4096

    // Projections
    sgemm_kernel<<<dim3((NH_ * D_) / 128, M / 128), 256>>>(X, Wq, Qp, M, NH_ * D_, HID_);
    sgemm_kernel<<<dim3((NKV_ * D_) / 128, M / 128), 256>>>(X, Wk, Kp, M, NKV_ * D_, HID_);
    sgemm_kernel<<<dim3((NKV_ * D_) / 128, M / 128), 256>>>(X, Wv, Vp, M, NKV_ * D_, HID_);

    // RoPE in-place
    rope_kernel<<<M * NH_, 64>>>(Qp, cosc, sinc, NH_);
    rope_kernel<<<M * NKV_, 64>>>(Kp, cosc, sinc, NKV_);

    // Flash attention
    cudaFuncSetAttribute(flash_kernel, cudaFuncAttributeMaxDynamicSharedMemorySize, FL_SMEM_BYTES);
    flash_kernel<<<dim3(S_ / 64, NH_, B_), 256, FL_SMEM_BYTES>>>(Qp, Kp, Vp, Ap);

    // Output projection
    sgemm_kernel<<<dim3(HID_ / 128, M / 128), 256>>>(Ap, Wo, out, M, HID_, NH_ * D_);
}

// round 3
// speedup vs baseline: 1.7477x; 1.7477x over previous
#include <cuda_runtime.h>
#include <cstdint>

// Problem constants
#define B_    2
#define S_    2048
#define HID_  4096
#define NH_   32
#define NKV_  8
#define D_    128

// ---------------- scratch (__device__ globals; allocation-free) -------------
__device__ float g_Q[(size_t)B_ * S_ * NH_ * D_];    // [B,S,NH,D]
__device__ float g_K[(size_t)B_ * S_ * NKV_ * D_];
__device__ float g_V[(size_t)B_ * S_ * NKV_ * D_];
__device__ float g_A[(size_t)B_ * S_ * NH_ * D_];    // attn out (tf32-rounded)
__device__ float g_Xr[(size_t)B_ * S_ * HID_];       // tf32-rounded hidden states
__device__ float g_Wqt[(size_t)(NH_ * D_) * HID_];   // [N,K] transposed+rounded
__device__ float g_Wkt[(size_t)(NKV_ * D_) * HID_];
__device__ float g_Wvt[(size_t)(NKV_ * D_) * HID_];
__device__ float g_Wot[(size_t)HID_ * (NH_ * D_)];

__device__ __forceinline__ float tf32rn(float x) {
    uint32_t u;
    asm("cvt.rn.tf32.f32 %0, %1;" : "=r"(u) : "f"(x));
    return __uint_as_float(u);
}

// ---------------- pre-pass kernels ------------------------------------------
__global__ void round_tf32_kernel(const float* __restrict__ in, float* __restrict__ out, int n4) {
    int i = blockIdx.x * blockDim.x + threadIdx.x;
    if (i < n4) {
        float4 v = ((const float4*)in)[i];
        v.x = tf32rn(v.x); v.y = tf32rn(v.y); v.z = tf32rn(v.z); v.w = tf32rn(v.w);
        ((float4*)out)[i] = v;
    }
}
// W[K,N] row-major -> Wt[N,K] row-major, tf32-rounded. block (32,8), grid (N/32, K/32)
__global__ void transpose_round_kernel(const float* __restrict__ W, float* __restrict__ Wt,
                                       int K, int N) {
    __shared__ float t[32][33];
    const int n0 = blockIdx.x * 32, k0 = blockIdx.y * 32;
    const int tx = threadIdx.x, ty = threadIdx.y;
#pragma unroll
    for (int j = 0; j < 32; j += 8)
        t[ty + j][tx] = W[(size_t)(k0 + ty + j) * N + n0 + tx];
    __syncthreads();
#pragma unroll
    for (int j = 0; j < 32; j += 8)
        Wt[(size_t)(n0 + ty + j) * K + k0 + tx] = tf32rn(t[tx][ty + j]);
}

// ---------------- tf32 mma.sync GEMM: C[M,N] = A[M,K] @ Bt[N,K]^T ------------
// CTA 128x128, BK=32, 256 threads (8 warps as 4x2: warpM rows of 32, warpN cols of 64).
// Fragments: mma.m16n8k8 tf32. Inputs pre-rounded to tf32 -> exact HW read.
#define BM 128
#define BN 128
#define BK 32
#define TSTR 36                      // padded row stride (floats)
#define TILE_FLOATS (128 * TSTR)     // per operand per buffer
#define GSM_FLOATS (4 * TILE_FLOATS) // A0,B0,A1,B1
#define GSM_BYTES (GSM_FLOATS * 4)

__device__ __forceinline__ void mma_tf32(float* c, const uint32_t* a, const uint32_t* b) {
    asm volatile(
        "mma.sync.aligned.m16n8k8.row.col.f32.tf32.tf32.f32 "
        "{%0,%1,%2,%3}, {%4,%5,%6,%7}, {%8,%9}, {%0,%1,%2,%3};"
        : "+f"(c[0]), "+f"(c[1]), "+f"(c[2]), "+f"(c[3])
        : "r"(a[0]), "r"(a[1]), "r"(a[2]), "r"(a[3]), "r"(b[0]), "r"(b[1]));
}

__device__ __forceinline__ void g2s_tile(const float* __restrict__ G, float* sm,
                                         int row0, int K, int k0, int tid) {
    // 128 rows x 32 floats, 4 float4 per thread
#pragma unroll
    for (int i = 0; i < 4; i++) {
        int lin = tid + i * 256;
        int r = lin >> 3, c = lin & 7;
        float4 v = *(const float4*)(G + (size_t)(row0 + r) * K + k0 + c * 4);
        *(float4*)(sm + r * TSTR + c * 4) = v;
    }
}

__global__ __launch_bounds__(256) void tc_gemm(const float* __restrict__ A,
                                               const float* __restrict__ Bt,
                                               float* __restrict__ C,
                                               int M, int N, int K) {
    extern __shared__ float sm[];
    float* As[2] = {sm, sm + 2 * TILE_FLOATS};
    float* Bs[2] = {sm + TILE_FLOATS, sm + 3 * TILE_FLOATS};

    const int tid = threadIdx.x;
    const int lane = tid & 31, wid = tid >> 5;
    const int warpM = wid & 3;        // 0..3 -> 32-row slab
    const int warpN = wid >> 2;       // 0..1 -> 64-col slab
    const int ty8 = lane >> 2;        // 0..7
    const int tx4 = lane & 3;         // 0..3
    const int bm = blockIdx.y * BM, bn = blockIdx.x * BN;

    float acc[2][8][4];
#pragma unroll
    for (int mi = 0; mi < 2; mi++)
#pragma unroll
        for (int ni = 0; ni < 8; ni++)
#pragma unroll
            for (int r = 0; r < 4; r++) acc[mi][ni][r] = 0.f;

    g2s_tile(A, As[0], bm, K, 0, tid);
    g2s_tile(Bt, Bs[0], bn, K, 0, tid);
    __syncthreads();

    const int NK = K / BK;
    for (int kt = 0; kt < NK; kt++) {
        const int buf = kt & 1;
        if (kt + 1 < NK) {
            g2s_tile(A, As[buf ^ 1], bm, K, (kt + 1) * BK, tid);
            g2s_tile(Bt, Bs[buf ^ 1], bn, K, (kt + 1) * BK, tid);
        }
        const float* Ab = As[buf];
        const float* Bb = Bs[buf];
#pragma unroll
        for (int ks = 0; ks < 4; ks++) {
            const int k8 = ks * 8;
            uint32_t af[2][4];
#pragma unroll
            for (int mi = 0; mi < 2; mi++) {
                const int rb = warpM * 32 + mi * 16 + ty8;
                af[mi][0] = __float_as_uint(Ab[(rb) * TSTR + k8 + tx4]);
                af[mi][1] = __float_as_uint(Ab[(rb + 8) * TSTR + k8 + tx4]);
                af[mi][2] = __float_as_uint(Ab[(rb) * TSTR + k8 + 4 + tx4]);
                af[mi][3] = __float_as_uint(Ab[(rb + 8) * TSTR + k8 + 4 + tx4]);
            }
            uint32_t bf[8][2];
#pragma unroll
            for (int ni = 0; ni < 8; ni++) {
                const int nc = warpN * 64 + ni * 8 + ty8;
                bf[ni][0] = __float_as_uint(Bb[nc * TSTR + k8 + tx4]);
                bf[ni][1] = __float_as_uint(Bb[nc * TSTR + k8 + 4 + tx4]);
            }
#pragma unroll
            for (int mi = 0; mi < 2; mi++)
#pragma unroll
                for (int ni = 0; ni < 8; ni++)
                    mma_tf32(acc[mi][ni], af[mi], bf[ni]);
        }
        __syncthreads();
    }

    // Epilogue: direct global stores (float2 per reg-pair)
#pragma unroll
    for (int mi = 0; mi < 2; mi++) {
        const int r0 = bm + warpM * 32 + mi * 16 + ty8;
#pragma unroll
        for (int ni = 0; ni < 8; ni++) {
            const int cc = bn + warpN * 64 + ni * 8 + 2 * tx4;
            *(float2*)(C + (size_t)r0 * N + cc)       = make_float2(acc[mi][ni][0], acc[mi][ni][1]);
            *(float2*)(C + (size_t)(r0 + 8) * N + cc) = make_float2(acc[mi][ni][2], acc[mi][ni][3]);
        }
    }
}

// ---------------- RoPE (in-place, Llama half-rotation) ----------------------
__global__ void rope_kernel(float* __restrict__ X,
                            const float* __restrict__ cosc,
                            const float* __restrict__ sinc, int H) {
    const int idx = blockIdx.x;
    const int s = (idx / H) % S_;
    const int d = threadIdx.x;
    float* row = X + (size_t)idx * D_;
    const float c0 = cosc[s * D_ + d];
    const float s0 = sinc[s * D_ + d];
    const float c1 = cosc[s * D_ + 64 + d];
    const float s1 = sinc[s * D_ + 64 + d];
    const float x1 = row[d];
    const float x2 = row[d + 64];
    row[d]      = x1 * c0 - x2 * s0;
    row[d + 64] = x2 * c1 + x1 * s1;
}

// ---------------- Causal flash attention (fp32 SIMT, online softmax) --------
#define QST 132
#define KST 68
#define VST 132
#define PST 68
#define FL_SMEM_BYTES ((64 * QST + 128 * KST + 64 * VST + 64 * PST) * 4)

__global__ __launch_bounds__(256) void flash_kernel(
    const float* __restrict__ Qg, const float* __restrict__ Kg,
    const float* __restrict__ Vg, float* __restrict__ Og) {
    extern __shared__ float smf[];
    float* Qs  = smf;
    float* Kst = Qs + 64 * QST;
    float* Vs  = Kst + 128 * KST;
    float* Ps  = Vs + 64 * VST;

    const int tid = threadIdx.x;
    const int tx = tid & 15;
    const int ty = tid >> 4;
    const int qt = blockIdx.x;
    const int h  = blockIdx.y;
    const int b  = blockIdx.z;
    const int kvh = h >> 2;
    const int qbase = qt * 64;
    const float scale = 0.08838834764831845f;

#pragma unroll
    for (int rep = 0; rep < 8; rep++) {
        int lin = rep * 256 + tid;
        int r = lin >> 5;
        int c4 = (lin & 31) << 2;
        float4 v = *(const float4*)(Qg + ((size_t)((b * S_ + qbase + r) * NH_ + h)) * D_ + c4);
        v.x *= scale; v.y *= scale; v.z *= scale; v.w *= scale;
        *(float4*)&Qs[r * QST + c4] = v;
    }

    float m_i[4], l_i[4], acc[4][8];
#pragma unroll
    for (int i = 0; i < 4; i++) {
        m_i[i] = -1e30f; l_i[i] = 0.f;
#pragma unroll
        for (int m = 0; m < 8; m++) acc[i][m] = 0.f;
    }

    for (int kt = 0; kt <= qt; kt++) {
        const int kbase = kt * 64;
#pragma unroll
        for (int rep = 0; rep < 8; rep++) {
            int lin = rep * 256 + tid;
            int c = lin >> 5;
            int k4 = (lin & 31) << 2;
            size_t gofs = ((size_t)((b * S_ + kbase + c) * NKV_ + kvh)) * D_ + k4;
            float4 kv = *(const float4*)(Kg + gofs);
            Kst[(k4 + 0) * KST + c] = kv.x;
            Kst[(k4 + 1) * KST + c] = kv.y;
            Kst[(k4 + 2) * KST + c] = kv.z;
            Kst[(k4 + 3) * KST + c] = kv.w;
            float4 vv = *(const float4*)(Vg + gofs);
            *(float4*)&Vs[c * VST + k4] = vv;
        }
        __syncthreads();

        float sc[4][4] = {};
#pragma unroll 8
        for (int k = 0; k < D_; k += 4) {
            float4 q0 = *(const float4*)&Qs[(ty * 4 + 0) * QST + k];
            float4 q1 = *(const float4*)&Qs[(ty * 4 + 1) * QST + k];
            float4 q2 = *(const float4*)&Qs[(ty * 4 + 2) * QST + k];
            float4 q3 = *(const float4*)&Qs[(ty * 4 + 3) * QST + k];
            float4 c0 = *(const float4*)&Kst[(k + 0) * KST + tx * 4];
            float4 c1 = *(const float4*)&Kst[(k + 1) * KST + tx * 4];
            float4 c2 = *(const float4*)&Kst[(k + 2) * KST + tx * 4];
            float4 c3 = *(const float4*)&Kst[(k + 3) * KST + tx * 4];
            float qv[4][4] = {{q0.x, q0.y, q0.z, q0.w}, {q1.x, q1.y, q1.z, q1.w},
                              {q2.x, q2.y, q2.z, q2.w}, {q3.x, q3.y, q3.z, q3.w}};
            float kv[4][4] = {{c0.x, c0.y, c0.z, c0.w}, {c1.x, c1.y, c1.z, c1.w},
                              {c2.x, c2.y, c2.z, c2.w}, {c3.x, c3.y, c3.z, c3.w}};
#pragma unroll
            for (int i = 0; i < 4; i++)
#pragma unroll
                for (int kk = 0; kk < 4; kk++)
#pragma unroll
                    for (int j = 0; j < 4; j++)
                        sc[i][j] += qv[i][kk] * kv[kk][j];
        }

        if (kt == qt) {
#pragma unroll
            for (int i = 0; i < 4; i++)
#pragma unroll
                for (int j = 0; j < 4; j++)
                    if (tx * 4 + j > ty * 4 + i) sc[i][j] = -1e30f;
        }

#pragma unroll
        for (int i = 0; i < 4; i++) {
            float mloc = fmaxf(fmaxf(sc[i][0], sc[i][1]), fmaxf(sc[i][2], sc[i][3]));
#pragma unroll
            for (int off = 1; off < 16; off <<= 1)
                mloc = fmaxf(mloc, __shfl_xor_sync(0xffffffffu, mloc, off));
            const float mnew = fmaxf(m_i[i], mloc);
            const float fac = __expf(m_i[i] - mnew);
            m_i[i] = mnew;
            l_i[i] *= fac;
#pragma unroll
            for (int m = 0; m < 8; m++) acc[i][m] *= fac;
            float rsum = 0.f;
#pragma unroll
            for (int j = 0; j < 4; j++) {
                float p = __expf(sc[i][j] - mnew);
                sc[i][j] = p;
                rsum += p;
            }
#pragma unroll
            for (int off = 1; off < 16; off <<= 1)
                rsum += __shfl_xor_sync(0xffffffffu, rsum, off);
            l_i[i] += rsum;
            *(float4*)&Ps[(ty * 4 + i) * PST + tx * 4] =
                make_float4(sc[i][0], sc[i][1], sc[i][2], sc[i][3]);
        }
        __syncthreads();

#pragma unroll 4
        for (int kk = 0; kk < 64; kk++) {
            float p0 = Ps[(ty * 4 + 0) * PST + kk];
            float p1 = Ps[(ty * 4 + 1) * PST + kk];
            float p2 = Ps[(ty * 4 + 2) * PST + kk];
            float p3 = Ps[(ty * 4 + 3) * PST + kk];
            float4 v0 = *(const float4*)&Vs[kk * VST + tx * 8];
            float4 v1 = *(const float4*)&Vs[kk * VST + tx * 8 + 4];
            float vv[8] = {v0.x, v0.y, v0.z, v0.w, v1.x, v1.y, v1.z, v1.w};
            float pp[4] = {p0, p1, p2, p3};
#pragma unroll
            for (int i = 0; i < 4; i++)
#pragma unroll
                for (int m = 0; m < 8; m++)
                    acc[i][m] += pp[i] * vv[m];
        }
        __syncthreads();
    }

    // Normalize + tf32-round (feeds mma O-proj) + store
#pragma unroll
    for (int i = 0; i < 4; i++) {
        const float inv = 1.0f / l_i[i];
        const int r = qbase + ty * 4 + i;
        float* op = Og + ((size_t)((b * S_ + r) * NH_ + h)) * D_ + tx * 8;
        *(float4*)op = make_float4(tf32rn(acc[i][0] * inv), tf32rn(acc[i][1] * inv),
                                   tf32rn(acc[i][2] * inv), tf32rn(acc[i][3] * inv));
        *(float4*)(op + 4) = make_float4(tf32rn(acc[i][4] * inv), tf32rn(acc[i][5] * inv),
                                         tf32rn(acc[i][6] * inv), tf32rn(acc[i][7] * inv));
    }
}

// ---------------- launch ----------------------------------------------------
extern "C" void kernel_launch(void* const* d_in, const int* in_sizes, int n_in,
                              void* d_out, int out_size) {
    const float* X    = (const float*)d_in[0];
    const float* Wq   = (const float*)d_in[1];
    const float* Wk   = (const float*)d_in[2];
    const float* Wv   = (const float*)d_in[3];
    const float* Wo   = (const float*)d_in[4];
    const float* cosc = (const float*)d_in[5];
    const float* sinc = (const float*)d_in[6];
    float* out = (float*)d_out;

    float *Qp, *Kp, *Vp, *Ap, *Xr, *Wqt, *Wkt, *Wvt, *Wot;
    cudaGetSymbolAddress((void**)&Qp, g_Q);
    cudaGetSymbolAddress((void**)&Kp, g_K);
    cudaGetSymbolAddress((void**)&Vp, g_V);
    cudaGetSymbolAddress((void**)&Ap, g_A);
    cudaGetSymbolAddress((void**)&Xr, g_Xr);
    cudaGetSymbolAddress((void**)&Wqt, g_Wqt);
    cudaGetSymbolAddress((void**)&Wkt, g_Wkt);
    cudaGetSymbolAddress((void**)&Wvt, g_Wvt);
    cudaGetSymbolAddress((void**)&Wot, g_Wot);

    const int M = B_ * S_;          // 4096
    const int NQ = NH_ * D_;        // 4096
    const int NKVD = NKV_ * D_;     // 1024

    // Pre-pass: round X; transpose+round weights to [N,K]
    {
        int n4 = M * HID_ / 4;
        round_tf32_kernel<<<(n4 + 255) / 256, 256>>>(X, Xr, n4);
        dim3 blk(32, 8);
        transpose_round_kernel<<<dim3(NQ / 32, HID_ / 32), blk>>>(Wq, Wqt, HID_, NQ);
        transpose_round_kernel<<<dim3(NKVD / 32, HID_ / 32), blk>>>(Wk, Wkt, HID_, NKVD);
        transpose_round_kernel<<<dim3(NKVD / 32, HID_ / 32), blk>>>(Wv, Wvt, HID_, NKVD);
        transpose_round_kernel<<<dim3(HID_ / 32, NQ / 32), blk>>>(Wo, Wot, NQ, HID_);
    }

    cudaFuncSetAttribute(tc_gemm, cudaFuncAttributeMaxDynamicSharedMemorySize, GSM_BYTES);

    // Projections (mma.sync tf32)
    tc_gemm<<<dim3(NQ / BN, M / BM), 256, GSM_BYTES>>>(Xr, Wqt, Qp, M, NQ, HID_);
    tc_gemm<<<dim3(NKVD / BN, M / BM), 256, GSM_BYTES>>>(Xr, Wkt, Kp, M, NKVD, HID_);
    tc_gemm<<<dim3(NKVD / BN, M / BM), 256, GSM_BYTES>>>(Xr, Wvt, Vp, M, NKVD, HID_);

    // RoPE in-place
    rope_kernel<<<M * NH_, 64>>>(Qp, cosc, sinc, NH_);
    rope_kernel<<<M * NKV_, 64>>>(Kp, cosc, sinc, NKV_);

    // Flash attention (fp32 SIMT)
    cudaFuncSetAttribute(flash_kernel, cudaFuncAttributeMaxDynamicSharedMemorySize, FL_SMEM_BYTES);
    flash_kernel<<<dim3(S_ / 64, NH_, B_), 256, FL_SMEM_BYTES>>>(Qp, Kp, Vp, Ap);

    // Output projection (mma.sync tf32)
    tc_gemm<<<dim3(HID_ / BN, M / BM), 256, GSM_BYTES>>>(Ap, Wot, out, M, HID_, NQ);
}

// round 4
// speedup vs baseline: 2.4654x; 1.4107x over previous
#include <cuda_runtime.h>
#include <cstdint>

// Problem constants
#define B_    2
#define S_    2048
#define HID_  4096
#define NH_   32
#define NKV_  8
#define D_    128

// ---------------- scratch (__device__ globals; allocation-free) -------------
__device__ float g_Q[(size_t)B_ * S_ * NH_ * D_];    // [B,S,NH,D]
__device__ float g_K[(size_t)B_ * S_ * NKV_ * D_];
__device__ float g_V[(size_t)B_ * S_ * NKV_ * D_];
__device__ float g_A[(size_t)B_ * S_ * NH_ * D_];    // attn out (tf32-rounded)
__device__ float g_Xr[(size_t)B_ * S_ * HID_];       // tf32-rounded hidden states
__device__ float g_Wqt[(size_t)(NH_ * D_) * HID_];   // [N,K] transposed+rounded
__device__ float g_Wkt[(size_t)(NKV_ * D_) * HID_];
__device__ float g_Wvt[(size_t)(NKV_ * D_) * HID_];
__device__ float g_Wot[(size_t)HID_ * (NH_ * D_)];

__device__ __forceinline__ float tf32rn(float x) {
    uint32_t u;
    asm("cvt.rn.tf32.f32 %0, %1;" : "=r"(u) : "f"(x));
    return __uint_as_float(u);
}

// ---------------- pre-pass kernels ------------------------------------------
__global__ void round_tf32_kernel(const float* __restrict__ in, float* __restrict__ out, int n4) {
    int i = blockIdx.x * blockDim.x + threadIdx.x;
    if (i < n4) {
        float4 v = ((const float4*)in)[i];
        v.x = tf32rn(v.x); v.y = tf32rn(v.y); v.z = tf32rn(v.z); v.w = tf32rn(v.w);
        ((float4*)out)[i] = v;
    }
}
// W[K,N] row-major -> Wt[N,K] row-major, tf32-rounded. block (32,8), grid (N/32, K/32)
__global__ void transpose_round_kernel(const float* __restrict__ W, float* __restrict__ Wt,
                                       int K, int N) {
    __shared__ float t[32][33];
    const int n0 = blockIdx.x * 32, k0 = blockIdx.y * 32;
    const int tx = threadIdx.x, ty = threadIdx.y;
#pragma unroll
    for (int j = 0; j < 32; j += 8)
        t[ty + j][tx] = W[(size_t)(k0 + ty + j) * N + n0 + tx];
    __syncthreads();
#pragma unroll
    for (int j = 0; j < 32; j += 8)
        Wt[(size_t)(n0 + ty + j) * K + k0 + tx] = tf32rn(t[tx][ty + j]);
}

// ---------------- mma helper -------------------------------------------------
__device__ __forceinline__ void mma_tf32(float* c, const uint32_t* a, const uint32_t* b) {
    asm volatile(
        "mma.sync.aligned.m16n8k8.row.col.f32.tf32.tf32.f32 "
        "{%0,%1,%2,%3}, {%4,%5,%6,%7}, {%8,%9}, {%0,%1,%2,%3};"
        : "+f"(c[0]), "+f"(c[1]), "+f"(c[2]), "+f"(c[3])
        : "r"(a[0]), "r"(a[1]), "r"(a[2]), "r"(a[3]), "r"(b[0]), "r"(b[1]));
}

// ---------------- tf32 mma.sync GEMM: C[M,N] = A[M,K] @ Bt[N,K]^T ------------
#define BM 128
#define BN 128
#define BK 32
#define TSTR 36
#define TILE_FLOATS (128 * TSTR)
#define GSM_BYTES (4 * TILE_FLOATS * 4)

__device__ __forceinline__ void g2s_tile(const float* __restrict__ G, float* sm,
                                         int row0, int K, int k0, int tid) {
#pragma unroll
    for (int i = 0; i < 4; i++) {
        int lin = tid + i * 256;
        int r = lin >> 3, c = lin & 7;
        float4 v = *(const float4*)(G + (size_t)(row0 + r) * K + k0 + c * 4);
        *(float4*)(sm + r * TSTR + c * 4) = v;
    }
}

__global__ __launch_bounds__(256) void tc_gemm(const float* __restrict__ A,
                                               const float* __restrict__ Bt,
                                               float* __restrict__ C,
                                               int M, int N, int K) {
    extern __shared__ float sm[];
    float* As[2] = {sm, sm + 2 * TILE_FLOATS};
    float* Bs[2] = {sm + TILE_FLOATS, sm + 3 * TILE_FLOATS};

    const int tid = threadIdx.x;
    const int lane = tid & 31, wid = tid >> 5;
    const int warpM = wid & 3;
    const int warpN = wid >> 2;
    const int ty8 = lane >> 2;
    const int tx4 = lane & 3;
    const int bm = blockIdx.y * BM, bn = blockIdx.x * BN;

    float acc[2][8][4];
#pragma unroll
    for (int mi = 0; mi < 2; mi++)
#pragma unroll
        for (int ni = 0; ni < 8; ni++)
#pragma unroll
            for (int r = 0; r < 4; r++) acc[mi][ni][r] = 0.f;

    g2s_tile(A, As[0], bm, K, 0, tid);
    g2s_tile(Bt, Bs[0], bn, K, 0, tid);
    __syncthreads();

    const int NK = K / BK;
    for (int kt = 0; kt < NK; kt++) {
        const int buf = kt & 1;
        if (kt + 1 < NK) {
            g2s_tile(A, As[buf ^ 1], bm, K, (kt + 1) * BK, tid);
            g2s_tile(Bt, Bs[buf ^ 1], bn, K, (kt + 1) * BK, tid);
        }
        const float* Ab = As[buf];
        const float* Bb = Bs[buf];
#pragma unroll
        for (int ks = 0; ks < 4; ks++) {
            const int k8 = ks * 8;
            uint32_t af[2][4];
#pragma unroll
            for (int mi = 0; mi < 2; mi++) {
                const int rb = warpM * 32 + mi * 16 + ty8;
                af[mi][0] = __float_as_uint(Ab[(rb) * TSTR + k8 + tx4]);
                af[mi][1] = __float_as_uint(Ab[(rb + 8) * TSTR + k8 + tx4]);
                af[mi][2] = __float_as_uint(Ab[(rb) * TSTR + k8 + 4 + tx4]);
                af[mi][3] = __float_as_uint(Ab[(rb + 8) * TSTR + k8 + 4 + tx4]);
            }
            uint32_t bf[8][2];
#pragma unroll
            for (int ni = 0; ni < 8; ni++) {
                const int nc = warpN * 64 + ni * 8 + ty8;
                bf[ni][0] = __float_as_uint(Bb[nc * TSTR + k8 + tx4]);
                bf[ni][1] = __float_as_uint(Bb[nc * TSTR + k8 + 4 + tx4]);
            }
#pragma unroll
            for (int mi = 0; mi < 2; mi++)
#pragma unroll
                for (int ni = 0; ni < 8; ni++)
                    mma_tf32(acc[mi][ni], af[mi], bf[ni]);
        }
        __syncthreads();
    }

#pragma unroll
    for (int mi = 0; mi < 2; mi++) {
        const int r0 = bm + warpM * 32 + mi * 16 + ty8;
#pragma unroll
        for (int ni = 0; ni < 8; ni++) {
            const int cc = bn + warpN * 64 + ni * 8 + 2 * tx4;
            *(float2*)(C + (size_t)r0 * N + cc)       = make_float2(acc[mi][ni][0], acc[mi][ni][1]);
            *(float2*)(C + (size_t)(r0 + 8) * N + cc) = make_float2(acc[mi][ni][2], acc[mi][ni][3]);
        }
    }
}

// ---------------- RoPE (in-place, Llama half-rotation) ----------------------
__global__ void rope_kernel(float* __restrict__ X,
                            const float* __restrict__ cosc,
                            const float* __restrict__ sinc, int H) {
    const int idx = blockIdx.x;
    const int s = (idx / H) % S_;
    const int d = threadIdx.x;
    float* row = X + (size_t)idx * D_;
    const float c0 = cosc[s * D_ + d];
    const float s0 = sinc[s * D_ + d];
    const float c1 = cosc[s * D_ + 64 + d];
    const float s1 = sinc[s * D_ + 64 + d];
    const float x1 = row[d];
    const float x2 = row[d + 64];
    row[d]      = x1 * c0 - x2 * s0;
    row[d + 64] = x2 * c1 + x1 * s1;
}

// ---------------- mma flash attention ----------------------------------------
// Q-tile 128 rows, K-tile 64 cols, 8 warps (warp = 16 q-rows).
// QK^T in tf32x2 (hi/lo split -> ~fp32 scores); softmax fp32; PV in tf32.
// smem floats:
#define QLO_STR 132
#define KS_STR  132
#define VS_STR  132
#define PS_STR  68
#define OFF_QLO 0
#define OFF_KH  (OFF_QLO + 128 * QLO_STR)     // 16896
#define OFF_KL  (OFF_KH + 64 * KS_STR)        // 25344
#define OFF_VS  (OFF_KL + 64 * KS_STR)        // 33792
#define OFF_PS  (OFF_VS + 64 * VS_STR)        // 42240
#define FL_FLOATS (OFF_PS + 128 * PS_STR)     // 50944
#define FL_SMEM_BYTES (FL_FLOATS * 4)         // 203776

__global__ __launch_bounds__(256) void flash_mma_kernel(
    const float* __restrict__ Qg, const float* __restrict__ Kg,
    const float* __restrict__ Vg, float* __restrict__ Og) {
    extern __shared__ float sm[];
    float* Qlo = sm + OFF_QLO;
    float* Kh  = sm + OFF_KH;
    float* Kl  = sm + OFF_KL;
    float* Vs  = sm + OFF_VS;
    float* Ps  = sm + OFF_PS;
    float* Qhstage = sm + OFF_KH;   // 16896 floats spanning Kh+Kl (temporary)

    const int tid = threadIdx.x;
    const int lane = tid & 31, wid = tid >> 5;
    const int ty8 = lane >> 2;      // 0..7
    const int tx4 = lane & 3;       // 0..3
    const int qt = blockIdx.x;      // 0..15 (128-row q tiles)
    const int h  = blockIdx.y;
    const int b  = blockIdx.z;
    const int kvh = h >> 2;
    const int qbase = qt * 128;
    const int wrow = wid * 16;      // warp's q-row slab
    const float scale = 0.08838834764831845f;

    // ---- stage Q: split into hi (Qhstage) / lo (Qlo) ----
#pragma unroll
    for (int i = 0; i < 16; i++) {
        int lin = i * 256 + tid;            // 4096 float4
        int r = lin >> 5;
        int c4 = (lin & 31) << 2;
        float4 v = *(const float4*)(Qg + ((size_t)((b * S_ + qbase + r) * NH_ + h)) * D_ + c4);
        float q[4] = {v.x * scale, v.y * scale, v.z * scale, v.w * scale};
#pragma unroll
        for (int j = 0; j < 4; j++) {
            float hi = tf32rn(q[j]);
            Qhstage[r * QLO_STR + c4 + j] = hi;
            Qlo[r * QLO_STR + c4 + j] = tf32rn(q[j] - hi);
        }
    }
    __syncthreads();

    // ---- Q_hi fragments in registers: 16 ksteps x 4 regs ----
    uint32_t qf[16][4];
#pragma unroll
    for (int ks = 0; ks < 16; ks++) {
        const int k8 = ks * 8;
        qf[ks][0] = __float_as_uint(Qhstage[(wrow + ty8) * QLO_STR + k8 + tx4]);
        qf[ks][1] = __float_as_uint(Qhstage[(wrow + ty8 + 8) * QLO_STR + k8 + tx4]);
        qf[ks][2] = __float_as_uint(Qhstage[(wrow + ty8) * QLO_STR + k8 + 4 + tx4]);
        qf[ks][3] = __float_as_uint(Qhstage[(wrow + ty8 + 8) * QLO_STR + k8 + 4 + tx4]);
    }
    __syncthreads();   // Qhstage region (Kh/Kl) now reusable

    float m_i[2] = {-1e30f, -1e30f};
    float l_i[2] = {0.f, 0.f};
    float oacc[16][4];
#pragma unroll
    for (int ni = 0; ni < 16; ni++)
#pragma unroll
        for (int r = 0; r < 4; r++) oacc[ni][r] = 0.f;

    const int NKT = 2 * qt + 2;
    for (int kt = 0; kt < NKT; kt++) {
        const int kbase = kt * 64;
        // ---- load K (hi/lo split) and V (tf32) tiles, natural [s][d] layout ----
#pragma unroll
        for (int i = 0; i < 8; i++) {
            int lin = i * 256 + tid;        // 2048 float4
            int r = lin >> 5;
            int c4 = (lin & 31) << 2;
            size_t gofs = ((size_t)((b * S_ + kbase + r) * NKV_ + kvh)) * D_ + c4;
            float4 kv = *(const float4*)(Kg + gofs);
            float kk[4] = {kv.x, kv.y, kv.z, kv.w};
#pragma unroll
            for (int j = 0; j < 4; j++) {
                float hi = tf32rn(kk[j]);
                Kh[r * KS_STR + c4 + j] = hi;
                Kl[r * KS_STR + c4 + j] = tf32rn(kk[j] - hi);
            }
            float4 vv = *(const float4*)(Vg + gofs);
            Vs[r * VS_STR + c4 + 0] = tf32rn(vv.x);
            Vs[r * VS_STR + c4 + 1] = tf32rn(vv.y);
            Vs[r * VS_STR + c4 + 2] = tf32rn(vv.z);
            Vs[r * VS_STR + c4 + 3] = tf32rn(vv.w);
        }
        __syncthreads();

        // ---- QK^T (tf32x2): sc = Qhi*Khi + Qhi*Klo + Qlo*Khi ----
        float sc[8][4];
#pragma unroll
        for (int ni = 0; ni < 8; ni++)
#pragma unroll
            for (int r = 0; r < 4; r++) sc[ni][r] = 0.f;

#pragma unroll
        for (int ks = 0; ks < 16; ks++) {
            const int k8 = ks * 8;
            uint32_t ql[4];
            ql[0] = __float_as_uint(Qlo[(wrow + ty8) * QLO_STR + k8 + tx4]);
            ql[1] = __float_as_uint(Qlo[(wrow + ty8 + 8) * QLO_STR + k8 + tx4]);
            ql[2] = __float_as_uint(Qlo[(wrow + ty8) * QLO_STR + k8 + 4 + tx4]);
            ql[3] = __float_as_uint(Qlo[(wrow + ty8 + 8) * QLO_STR + k8 + 4 + tx4]);
#pragma unroll
            for (int ni = 0; ni < 8; ni++) {
                const int n = ni * 8 + ty8;
                uint32_t bh[2], bl[2];
                bh[0] = __float_as_uint(Kh[n * KS_STR + k8 + tx4]);
                bh[1] = __float_as_uint(Kh[n * KS_STR + k8 + 4 + tx4]);
                bl[0] = __float_as_uint(Kl[n * KS_STR + k8 + tx4]);
                bl[1] = __float_as_uint(Kl[n * KS_STR + k8 + 4 + tx4]);
                mma_tf32(sc[ni], qf[ks], bh);
                mma_tf32(sc[ni], qf[ks], bl);
                mma_tf32(sc[ni], ql, bh);
            }
        }

        // ---- causal mask (only possible on the last two k-tiles of this q-tile)
        if (kbase + 63 > qbase) {
#pragma unroll
            for (int ni = 0; ni < 8; ni++) {
#pragma unroll
                for (int r = 0; r < 4; r++) {
                    int row = qbase + wrow + ty8 + ((r >= 2) ? 8 : 0);
                    int col = kbase + ni * 8 + 2 * tx4 + (r & 1);
                    if (col > row) sc[ni][r] = -1e30f;
                }
            }
        }

        // ---- online softmax (rows ty8 / ty8+8; row spread over 4 lanes tx4) ----
#pragma unroll
        for (int rh = 0; rh < 2; rh++) {
            const int i0 = rh * 2, i1 = rh * 2 + 1;
            float mloc = -1e30f;
#pragma unroll
            for (int ni = 0; ni < 8; ni++)
                mloc = fmaxf(mloc, fmaxf(sc[ni][i0], sc[ni][i1]));
            mloc = fmaxf(mloc, __shfl_xor_sync(0xffffffffu, mloc, 1));
            mloc = fmaxf(mloc, __shfl_xor_sync(0xffffffffu, mloc, 2));
            const float mnew = fmaxf(m_i[rh], mloc);
            const float fac = __expf(m_i[rh] - mnew);
            m_i[rh] = mnew;
            float rsum = 0.f;
#pragma unroll
            for (int ni = 0; ni < 8; ni++) {
                float p0 = __expf(sc[ni][i0] - mnew);
                float p1 = __expf(sc[ni][i1] - mnew);
                sc[ni][i0] = p0; sc[ni][i1] = p1;
                rsum += p0 + p1;
            }
            rsum += __shfl_xor_sync(0xffffffffu, rsum, 1);
            rsum += __shfl_xor_sync(0xffffffffu, rsum, 2);
            l_i[rh] = l_i[rh] * fac + rsum;
#pragma unroll
            for (int ni = 0; ni < 16; ni++) {
                oacc[ni][i0] *= fac;
                oacc[ni][i1] *= fac;
            }
        }

        // ---- write P (tf32) to smem for A-frag remap ----
#pragma unroll
        for (int ni = 0; ni < 8; ni++) {
            const int cc = ni * 8 + 2 * tx4;
            *(float2*)&Ps[(wrow + ty8) * PS_STR + cc] =
                make_float2(tf32rn(sc[ni][0]), tf32rn(sc[ni][1]));
            *(float2*)&Ps[(wrow + ty8 + 8) * PS_STR + cc] =
                make_float2(tf32rn(sc[ni][2]), tf32rn(sc[ni][3]));
        }
        __syncwarp();

        // ---- PV: oacc += P @ V  (V natural [s][d]; B-frag reads cols) ----
#pragma unroll
        for (int ks = 0; ks < 8; ks++) {
            const int k8 = ks * 8;
            uint32_t af[4];
            af[0] = __float_as_uint(Ps[(wrow + ty8) * PS_STR + k8 + tx4]);
            af[1] = __float_as_uint(Ps[(wrow + ty8 + 8) * PS_STR + k8 + tx4]);
            af[2] = __float_as_uint(Ps[(wrow + ty8) * PS_STR + k8 + 4 + tx4]);
            af[3] = __float_as_uint(Ps[(wrow + ty8 + 8) * PS_STR + k8 + 4 + tx4]);
#pragma unroll
            for (int ni = 0; ni < 16; ni++) {
                const int n = ni * 8 + ty8;     // d-column
                uint32_t bf[2];
                bf[0] = __float_as_uint(Vs[(k8 + tx4) * VS_STR + n]);
                bf[1] = __float_as_uint(Vs[(k8 + 4 + tx4) * VS_STR + n]);
                mma_tf32(oacc[ni], af, bf);
            }
        }
        __syncthreads();
    }

    // ---- epilogue: normalize, tf32-round (feeds O-proj mma), store ----
    const float inv0 = 1.0f / l_i[0];
    const float inv1 = 1.0f / l_i[1];
    const int r0 = qbase + wrow + ty8;
#pragma unroll
    for (int ni = 0; ni < 16; ni++) {
        const int cc = ni * 8 + 2 * tx4;
        float* p0 = Og + ((size_t)((b * S_ + r0) * NH_ + h)) * D_ + cc;
        float* p1 = Og + ((size_t)((b * S_ + r0 + 8) * NH_ + h)) * D_ + cc;
        *(float2*)p0 = make_float2(tf32rn(oacc[ni][0] * inv0), tf32rn(oacc[ni][1] * inv0));
        *(float2*)p1 = make_float2(tf32rn(oacc[ni][2] * inv1), tf32rn(oacc[ni][3] * inv1));
    }
}

// ---------------- launch ----------------------------------------------------
extern "C" void kernel_launch(void* const* d_in, const int* in_sizes, int n_in,
                              void* d_out, int out_size) {
    const float* X    = (const float*)d_in[0];
    const float* Wq   = (const float*)d_in[1];
    const float* Wk   = (const float*)d_in[2];
    const float* Wv   = (const float*)d_in[3];
    const float* Wo   = (const float*)d_in[4];
    const float* cosc = (const float*)d_in[5];
    const float* sinc = (const float*)d_in[6];
    float* out = (float*)d_out;

    float *Qp, *Kp, *Vp, *Ap, *Xr, *Wqt, *Wkt, *Wvt, *Wot;
    cudaGetSymbolAddress((void**)&Qp, g_Q);
    cudaGetSymbolAddress((void**)&Kp, g_K);
    cudaGetSymbolAddress((void**)&Vp, g_V);
    cudaGetSymbolAddress((void**)&Ap, g_A);
    cudaGetSymbolAddress((void**)&Xr, g_Xr);
    cudaGetSymbolAddress((void**)&Wqt, g_Wqt);
    cudaGetSymbolAddress((void**)&Wkt, g_Wkt);
    cudaGetSymbolAddress((void**)&Wvt, g_Wvt);
    cudaGetSymbolAddress((void**)&Wot, g_Wot);

    const int M = B_ * S_;          // 4096
    const int NQ = NH_ * D_;        // 4096
    const int NKVD = NKV_ * D_;     // 1024

    {
        int n4 = M * HID_ / 4;
        round_tf32_kernel<<<(n4 + 255) / 256, 256>>>(X, Xr, n4);
        dim3 blk(32, 8);
        transpose_round_kernel<<<dim3(NQ / 32, HID_ / 32), blk>>>(Wq, Wqt, HID_, NQ);
        transpose_round_kernel<<<dim3(NKVD / 32, HID_ / 32), blk>>>(Wk, Wkt, HID_, NKVD);
        transpose_round_kernel<<<dim3(NKVD / 32, HID_ / 32), blk>>>(Wv, Wvt, HID_, NKVD);
        transpose_round_kernel<<<dim3(HID_ / 32, NQ / 32), blk>>>(Wo, Wot, NQ, HID_);
    }

    cudaFuncSetAttribute(tc_gemm, cudaFuncAttributeMaxDynamicSharedMemorySize, GSM_BYTES);

    tc_gemm<<<dim3(NQ / BN, M / BM), 256, GSM_BYTES>>>(Xr, Wqt, Qp, M, NQ, HID_);
    tc_gemm<<<dim3(NKVD / BN, M / BM), 256, GSM_BYTES>>>(Xr, Wkt, Kp, M, NKVD, HID_);
    tc_gemm<<<dim3(NKVD / BN, M / BM), 256, GSM_BYTES>>>(Xr, Wvt, Vp, M, NKVD, HID_);

    rope_kernel<<<M * NH_, 64>>>(Qp, cosc, sinc, NH_);
    rope_kernel<<<M * NKV_, 64>>>(Kp, cosc, sinc, NKV_);

    cudaFuncSetAttribute(flash_mma_kernel, cudaFuncAttributeMaxDynamicSharedMemorySize, FL_SMEM_BYTES);
    flash_mma_kernel<<<dim3(S_ / 128, NH_, B_), 256, FL_SMEM_BYTES>>>(Qp, Kp, Vp, Ap);

    tc_gemm<<<dim3(HID_ / BN, M / BM), 256, GSM_BYTES>>>(Ap, Wot, out, M, HID_, NQ);
}